// round 1
// baseline (speedup 1.0000x reference)
#include <cuda_runtime.h>
#include <cuda_bf16.h>

#define B_ROWS   8192
#define F_DIM    512
#define N_INT    1023
#define N_PAD    1024
#define N_LEAVES 1024
#define LEAF_D   64
#define DEPTH    10

// Scratch (allocation-free): P = sigmoid(xW+b) padded to 1024 cols; PROB = leaf probs.
__device__ float g_P[B_ROWS * N_PAD];
__device__ float g_PROB[B_ROWS * N_LEAVES];

// ---------------------------------------------------------------------------
// Kernel 1: P[8192,1024] = sigmoid(x[8192,512] @ W[512,1023] + b), col 1023 junk.
// BM=128, BN=128, BK=8, 256 threads, 8x8 thread tile. grid = (8, 64).
// ---------------------------------------------------------------------------
__global__ __launch_bounds__(256, 2)
void gemm1_sigmoid_kernel(const float* __restrict__ x,
                          const float* __restrict__ W,
                          const float* __restrict__ bias)
{
    __shared__ float As[8][132];   // [k][m], padded
    __shared__ float Bs[8][132];   // [k][n], padded

    const int tid  = threadIdx.x;
    const int tx   = tid & 15;     // 0..15 -> n dir
    const int ty   = tid >> 4;     // 0..15 -> m dir
    const int row0 = blockIdx.y * 128;
    const int col0 = blockIdx.x * 128;

    float acc[8][8];
    #pragma unroll
    for (int i = 0; i < 8; ++i)
        #pragma unroll
        for (int j = 0; j < 8; ++j) acc[i][j] = 0.0f;

    // A loader: each thread loads one float4 (4 k's of one row) per k-tile.
    const int am  = tid >> 1;            // 0..127 (row within tile)
    const int akq = (tid & 1) * 4;       // 0 or 4 (k offset)
    const float* aptr = x + (size_t)(row0 + am) * F_DIM + akq;

    for (int bk = 0; bk < F_DIM; bk += 8) {
        float4 av = *(const float4*)(aptr + bk);
        float bv[4];
        #pragma unroll
        for (int i = 0; i < 4; ++i) {
            int idx = tid + i * 256;          // 0..1023
            int k   = idx >> 7;               // 0..7
            int c   = idx & 127;              // 0..127
            int gc  = col0 + c;
            bv[i] = (gc < N_INT) ? W[(size_t)(bk + k) * N_INT + gc] : 0.0f;
        }
        __syncthreads();   // previous tile fully consumed
        As[akq + 0][am] = av.x;
        As[akq + 1][am] = av.y;
        As[akq + 2][am] = av.z;
        As[akq + 3][am] = av.w;
        #pragma unroll
        for (int i = 0; i < 4; ++i) {
            int idx = tid + i * 256;
            Bs[idx >> 7][idx & 127] = bv[i];
        }
        __syncthreads();

        #pragma unroll
        for (int kk = 0; kk < 8; ++kk) {
            float4 a0 = *(const float4*)&As[kk][ty * 8];
            float4 a1 = *(const float4*)&As[kk][ty * 8 + 4];
            float4 b0 = *(const float4*)&Bs[kk][tx * 8];
            float4 b1 = *(const float4*)&Bs[kk][tx * 8 + 4];
            float a[8] = {a0.x, a0.y, a0.z, a0.w, a1.x, a1.y, a1.z, a1.w};
            float b[8] = {b0.x, b0.y, b0.z, b0.w, b1.x, b1.y, b1.z, b1.w};
            #pragma unroll
            for (int i = 0; i < 8; ++i)
                #pragma unroll
                for (int j = 0; j < 8; ++j)
                    acc[i][j] += a[i] * b[j];
        }
    }

    // Epilogue: add bias, sigmoid, store into padded P (col 1023 never read).
    float bb[8];
    #pragma unroll
    for (int j = 0; j < 8; ++j) {
        int gc = col0 + tx * 8 + j;
        bb[j] = (gc < N_INT) ? bias[gc] : 0.0f;
    }
    #pragma unroll
    for (int i = 0; i < 8; ++i) {
        int gr = row0 + ty * 8 + i;
        float* prow = g_P + (size_t)gr * N_PAD + col0 + tx * 8;
        #pragma unroll
        for (int j = 0; j < 8; ++j) {
            float z = acc[i][j] + bb[j];
            prow[j] = 1.0f / (1.0f + __expf(-z));
        }
    }
}

// ---------------------------------------------------------------------------
// Kernel 2: tree expansion. PROB[row][l] = prod over 10 levels of path factors.
// 8 rows per CTA, 256 threads, p rows staged in smem. grid = 1024.
// ---------------------------------------------------------------------------
__global__ __launch_bounds__(256)
void tree_expand_kernel()
{
    __shared__ float p_s[8 * 1024];
    const int tid  = threadIdx.x;
    const int row0 = blockIdx.x * 8;

    const float* src = g_P + (size_t)row0 * N_PAD;
    #pragma unroll
    for (int i = 0; i < 32; ++i)
        p_s[tid + i * 256] = src[tid + i * 256];
    __syncthreads();

    float* dst = g_PROB + (size_t)row0 * N_LEAVES;
    #pragma unroll
    for (int i = 0; i < 32; ++i) {
        int idx = tid + i * 256;
        int r   = idx >> 10;
        int l   = idx & 1023;
        const float* pr = p_s + (r << 10);
        float w = 1.0f;
        #pragma unroll
        for (int lvl = 0; lvl < DEPTH; ++lvl) {
            int node = (1 << lvl) - 1 + (l >> (DEPTH - lvl));
            float pv = pr[node];
            int bit  = (l >> (DEPTH - 1 - lvl)) & 1;
            w *= bit ? (1.0f - pv) : pv;
        }
        dst[idx] = w;
    }
}

// ---------------------------------------------------------------------------
// Kernel 3: out[8192,64] = PROB[8192,1024] @ leaves[1024,64].
// BM=64, BN=64, BK=16, 256 threads, 4x4 thread tile. grid = 128.
// ---------------------------------------------------------------------------
__global__ __launch_bounds__(256, 4)
void gemm2_kernel(const float* __restrict__ leaves, float* __restrict__ out)
{
    __shared__ float As[16][68];   // [k][m], padded
    __shared__ float Bs[16][64];   // [k][n]

    const int tid  = threadIdx.x;
    const int tx   = tid & 15;
    const int ty   = tid >> 4;
    const int row0 = blockIdx.x * 64;

    float acc[4][4];
    #pragma unroll
    for (int i = 0; i < 4; ++i)
        #pragma unroll
        for (int j = 0; j < 4; ++j) acc[i][j] = 0.0f;

    const int am  = tid >> 2;          // 0..63
    const int akq = (tid & 3) * 4;     // 0,4,8,12
    const float* aptr = g_PROB + (size_t)(row0 + am) * N_LEAVES + akq;

    for (int bk = 0; bk < N_LEAVES; bk += 16) {
        float4 av = *(const float4*)(aptr + bk);
        float bv[4];
        #pragma unroll
        for (int i = 0; i < 4; ++i) {
            int idx = tid + i * 256;           // 0..1023
            bv[i] = leaves[(size_t)(bk + (idx >> 6)) * LEAF_D + (idx & 63)];
        }
        __syncthreads();
        As[akq + 0][am] = av.x;
        As[akq + 1][am] = av.y;
        As[akq + 2][am] = av.z;
        As[akq + 3][am] = av.w;
        #pragma unroll
        for (int i = 0; i < 4; ++i) {
            int idx = tid + i * 256;
            Bs[idx >> 6][idx & 63] = bv[i];
        }
        __syncthreads();

        #pragma unroll
        for (int kk = 0; kk < 16; ++kk) {
            float4 a = *(const float4*)&As[kk][ty * 4];
            float4 b = *(const float4*)&Bs[kk][tx * 4];
            float av4[4] = {a.x, a.y, a.z, a.w};
            float bv4[4] = {b.x, b.y, b.z, b.w};
            #pragma unroll
            for (int i = 0; i < 4; ++i)
                #pragma unroll
                for (int j = 0; j < 4; ++j)
                    acc[i][j] += av4[i] * bv4[j];
        }
    }

    #pragma unroll
    for (int i = 0; i < 4; ++i) {
        int gr = row0 + ty * 4 + i;
        float* orow = out + (size_t)gr * LEAF_D + tx * 4;
        #pragma unroll
        for (int j = 0; j < 4; ++j)
            orow[j] = acc[i][j];
    }
}

// ---------------------------------------------------------------------------
extern "C" void kernel_launch(void* const* d_in, const int* in_sizes, int n_in,
                              void* d_out, int out_size)
{
    const float* x      = (const float*)d_in[0];   // [8192, 512]
    const float* W      = (const float*)d_in[1];   // [512, 1023]
    const float* bias   = (const float*)d_in[2];   // [1023]
    const float* leaves = (const float*)d_in[3];   // [1024, 64]
    float*       out    = (float*)d_out;           // [8192, 64]

    gemm1_sigmoid_kernel<<<dim3(8, 64), 256>>>(x, W, bias);
    tree_expand_kernel<<<1024, 256>>>();
    gemm2_kernel<<<128, 256>>>(leaves, out);
}

// round 3
// speedup vs baseline: 1.9253x; 1.9253x over previous
#include <cuda_runtime.h>
#include <cuda_bf16.h>
#include <cstdint>

#define B_ROWS   8192
#define F_DIM    512
#define N_INT    1023
#define N_PAD    1024
#define N_LEAVES 1024
#define LEAF_D   64
#define DEPTH    10

// Scratch (allocation-free device global)
__device__ float g_P[B_ROWS * N_PAD];   // sigmoid(xW+b), col 1023 junk

__device__ __forceinline__ float tf32_round(float v) {
    float r;
    asm("cvt.rna.tf32.f32 %0, %1;" : "=f"(r) : "f"(v));
    return r;
}

// m16n8k8 tf32 MMA (sm_80+ PTX — compiles for plain compute_103)
__device__ __forceinline__ void mma_tf32(float* d, const float* a, const float* b) {
    asm volatile(
        "mma.sync.aligned.m16n8k8.row.col.f32.tf32.tf32.f32 "
        "{%0,%1,%2,%3}, {%4,%5,%6,%7}, {%8,%9}, {%0,%1,%2,%3};"
        : "+f"(d[0]), "+f"(d[1]), "+f"(d[2]), "+f"(d[3])
        : "r"(__float_as_uint(a[0])), "r"(__float_as_uint(a[1])),
          "r"(__float_as_uint(a[2])), "r"(__float_as_uint(a[3])),
          "r"(__float_as_uint(b[0])), "r"(__float_as_uint(b[1])));
}

// ===========================================================================
// Kernel 1: P = sigmoid(x @ W + b) via mma.sync tf32.
// BM=128, BN=128, BK=16. 256 threads = 8 warps (2M x 4N), warp tile 64x32.
// Double-buffered smem; A pad 20, B pad 136 (conflict-free frag loads).
// grid = (8, 64).
// ===========================================================================
#define AS_LD 20
#define BS_LD 136

__global__ __launch_bounds__(256)
void gemm1_mma_kernel(const float* __restrict__ x, const float* __restrict__ W,
                      const float* __restrict__ bias)
{
    __shared__ float As[2][128 * AS_LD];
    __shared__ float Bs[2][16 * BS_LD];

    const int tid  = threadIdx.x;
    const int lane = tid & 31;
    const int wid  = tid >> 5;
    const int wm   = (wid & 1) * 64;     // warp M origin in tile
    const int wn   = (wid >> 1) * 32;    // warp N origin in tile
    const int row0 = blockIdx.y * 128;
    const int col0 = blockIdx.x * 128;
    const int g    = lane >> 2;          // 0..7
    const int t    = lane & 3;           // 0..3

    float acc[4][4][4];
    #pragma unroll
    for (int mt = 0; mt < 4; ++mt)
        #pragma unroll
        for (int nt = 0; nt < 4; ++nt)
            #pragma unroll
            for (int i = 0; i < 4; ++i) acc[mt][nt][i] = 0.0f;

    // x loader: thread covers rows xm, xm+64, k-quad xk
    const int xm = tid >> 2;
    const int xk = (tid & 3) * 4;
    const float* xp = x + (size_t)(row0 + xm) * F_DIM + xk;
    // W loader: row wk (0..15), 8 cols starting wn0
    const int wk  = tid >> 4;
    const int wn0 = (tid & 15) * 8;

    float4 xa, xb;
    float  wv[8];

    // prefetch tile 0
    xa = *(const float4*)(xp);
    xb = *(const float4*)(xp + 64 * F_DIM);
    {
        const float* wrow = W + (size_t)wk * N_INT + col0 + wn0;
        #pragma unroll
        for (int j = 0; j < 8; ++j)
            wv[j] = (col0 + wn0 + j < N_INT) ? wrow[j] : 0.0f;
    }

    int buf = 0;
    // store tile 0
    {
        float* a0 = &As[buf][xm * AS_LD + xk];
        float* a1 = &As[buf][(xm + 64) * AS_LD + xk];
        a0[0] = tf32_round(xa.x); a0[1] = tf32_round(xa.y);
        a0[2] = tf32_round(xa.z); a0[3] = tf32_round(xa.w);
        a1[0] = tf32_round(xb.x); a1[1] = tf32_round(xb.y);
        a1[2] = tf32_round(xb.z); a1[3] = tf32_round(xb.w);
        float* bp = &Bs[buf][wk * BS_LD + wn0];
        #pragma unroll
        for (int j = 0; j < 8; ++j) bp[j] = tf32_round(wv[j]);
    }
    __syncthreads();

    for (int tile = 0; tile < 32; ++tile) {
        // prefetch next tile into regs
        if (tile < 31) {
            const int bk = (tile + 1) * 16;
            xa = *(const float4*)(xp + bk);
            xb = *(const float4*)(xp + 64 * F_DIM + bk);
            const float* wrow = W + (size_t)(bk + wk) * N_INT + col0 + wn0;
            #pragma unroll
            for (int j = 0; j < 8; ++j)
                wv[j] = (col0 + wn0 + j < N_INT) ? wrow[j] : 0.0f;
        }
        // compute current tile (two k8 steps)
        #pragma unroll
        for (int kk = 0; kk < 16; kk += 8) {
            float a[4][4], b[4][2];
            #pragma unroll
            for (int mt = 0; mt < 4; ++mt) {
                const float* ap = &As[buf][(wm + mt * 16 + g) * AS_LD + kk + t];
                a[mt][0] = ap[0];
                a[mt][1] = ap[8 * AS_LD];
                a[mt][2] = ap[4];
                a[mt][3] = ap[8 * AS_LD + 4];
            }
            #pragma unroll
            for (int nt = 0; nt < 4; ++nt) {
                const float* bp = &Bs[buf][(kk + t) * BS_LD + wn + nt * 8 + g];
                b[nt][0] = bp[0];
                b[nt][1] = bp[4 * BS_LD];
            }
            #pragma unroll
            for (int mt = 0; mt < 4; ++mt)
                #pragma unroll
                for (int nt = 0; nt < 4; ++nt)
                    mma_tf32(acc[mt][nt], a[mt], b[nt]);
        }
        // store next tile into other buffer
        if (tile < 31) {
            const int nbuf = buf ^ 1;
            float* a0 = &As[nbuf][xm * AS_LD + xk];
            float* a1 = &As[nbuf][(xm + 64) * AS_LD + xk];
            a0[0] = tf32_round(xa.x); a0[1] = tf32_round(xa.y);
            a0[2] = tf32_round(xa.z); a0[3] = tf32_round(xa.w);
            a1[0] = tf32_round(xb.x); a1[1] = tf32_round(xb.y);
            a1[2] = tf32_round(xb.z); a1[3] = tf32_round(xb.w);
            float* bp = &Bs[nbuf][wk * BS_LD + wn0];
            #pragma unroll
            for (int j = 0; j < 8; ++j) bp[j] = tf32_round(wv[j]);
            __syncthreads();
            buf = nbuf;
        }
    }

    // Epilogue: bias + sigmoid, write g_P
    #pragma unroll
    for (int nt = 0; nt < 4; ++nt) {
        const int col = col0 + wn + nt * 8 + 2 * t;
        const float b0 = (col     < N_INT) ? bias[col]     : 0.0f;
        const float b1 = (col + 1 < N_INT) ? bias[col + 1] : 0.0f;
        #pragma unroll
        for (int mt = 0; mt < 4; ++mt) {
            const int row = row0 + wm + mt * 16 + g;
            float2 v0, v1;
            v0.x = 1.0f / (1.0f + __expf(-(acc[mt][nt][0] + b0)));
            v0.y = 1.0f / (1.0f + __expf(-(acc[mt][nt][1] + b1)));
            v1.x = 1.0f / (1.0f + __expf(-(acc[mt][nt][2] + b0)));
            v1.y = 1.0f / (1.0f + __expf(-(acc[mt][nt][3] + b1)));
            *(float2*)(g_P + (size_t)row * N_PAD + col)       = v0;
            *(float2*)(g_P + (size_t)(row + 8) * N_PAD + col) = v1;
        }
    }
}

// ===========================================================================
// Kernel 2 (fused): tree expansion + out = PROB @ leaves.
// 8 rows per CTA, 256 threads, grid = 1024.
// Phase A: load p (8x1024) to smem (pad 1032).
// Phase B: leaf probs -> prob_s[k][8] (transposed for vector loads).
// Phase C: K-split GEMM (8 chunks x 128), smem partial reduction.
// ===========================================================================
#define PS_LD 1032
#define FUSED_SMEM ((8 * PS_LD + 8 * 1024) * 4)

__global__ __launch_bounds__(256)
void fused_tree_gemm2(const float* __restrict__ leaves, float* __restrict__ out)
{
    extern __shared__ float sm[];
    float* p_s    = sm;               // [8][PS_LD]
    float* prob_s = sm + 8 * PS_LD;   // [1024][8]
    const int tid  = threadIdx.x;
    const int row0 = blockIdx.x * 8;

    // Phase A: load p rows
    const float* src = g_P + (size_t)row0 * N_PAD;
    #pragma unroll
    for (int i = 0; i < 32; ++i) {
        int idx = tid + i * 256;           // 0..8191
        int r = idx >> 10, c = idx & 1023;
        p_s[r * PS_LD + c] = src[idx];
    }
    __syncthreads();

    // Phase B: expansion. idx -> (l = idx>>3, r = idx&7); write prob_s[l*8+r]
    #pragma unroll
    for (int i = 0; i < 32; ++i) {
        int idx = i * 256 + tid;
        int r = idx & 7;
        int l = idx >> 3;
        const float* pr = p_s + r * PS_LD;
        float w = 1.0f;
        #pragma unroll
        for (int lvl = 0; lvl < DEPTH; ++lvl) {
            int node = (1 << lvl) - 1 + (l >> (DEPTH - lvl));
            float pv = pr[node];
            int bit  = (l >> (DEPTH - 1 - lvl)) & 1;
            w *= bit ? (1.0f - pv) : pv;
        }
        prob_s[l * 8 + r] = w;
    }
    __syncthreads();

    // Phase C: GEMM. warp w handles K-chunk w (128 k's); lane -> 2 output cols.
    const int kc   = tid >> 5;
    const int ln   = tid & 31;
    const int c2   = ln * 2;
    float2 acc[8];
    #pragma unroll
    for (int r = 0; r < 8; ++r) { acc[r].x = 0.0f; acc[r].y = 0.0f; }

    const float* lv = leaves + (size_t)(kc * 128) * LEAF_D + c2;
    const float* pp = prob_s + kc * 128 * 8;
    #pragma unroll 4
    for (int k = 0; k < 128; ++k) {
        const float2 l2 = *(const float2*)(lv + (size_t)k * LEAF_D);
        const float4 pa = *(const float4*)(pp + k * 8);
        const float4 pb = *(const float4*)(pp + k * 8 + 4);
        acc[0].x += pa.x * l2.x; acc[0].y += pa.x * l2.y;
        acc[1].x += pa.y * l2.x; acc[1].y += pa.y * l2.y;
        acc[2].x += pa.z * l2.x; acc[2].y += pa.z * l2.y;
        acc[3].x += pa.w * l2.x; acc[3].y += pa.w * l2.y;
        acc[4].x += pb.x * l2.x; acc[4].y += pb.x * l2.y;
        acc[5].x += pb.y * l2.x; acc[5].y += pb.y * l2.y;
        acc[6].x += pb.z * l2.x; acc[6].y += pb.z * l2.y;
        acc[7].x += pb.w * l2.x; acc[7].y += pb.w * l2.y;
    }

    // partials -> p_s scratch (reused), then reduce over 8 chunks
    float2* scr = (float2*)p_s;
    __syncthreads();   // everyone done reading p_s (phase B) & prob_s
    #pragma unroll
    for (int r = 0; r < 8; ++r)
        scr[(r * 8 + kc) * 32 + ln] = acc[r];
    __syncthreads();

    {
        const int r = tid >> 5;
        float2 s; s.x = 0.0f; s.y = 0.0f;
        #pragma unroll
        for (int q = 0; q < 8; ++q) {
            float2 v = scr[(r * 8 + q) * 32 + ln];
            s.x += v.x; s.y += v.y;
        }
        *(float2*)(out + (size_t)(row0 + r) * LEAF_D + c2) = s;
    }
}

// ===========================================================================
extern "C" void kernel_launch(void* const* d_in, const int* in_sizes, int n_in,
                              void* d_out, int out_size)
{
    const float* x      = (const float*)d_in[0];   // [8192, 512]
    const float* W      = (const float*)d_in[1];   // [512, 1023]
    const float* bias   = (const float*)d_in[2];   // [1023]
    const float* leaves = (const float*)d_in[3];   // [1024, 64]
    float*       out    = (float*)d_out;           // [8192, 64]

    cudaFuncSetAttribute(fused_tree_gemm2,
                         cudaFuncAttributeMaxDynamicSharedMemorySize, FUSED_SMEM);

    gemm1_mma_kernel<<<dim3(8, 64), 256>>>(x, W, bias);
    fused_tree_gemm2<<<1024, 256, FUSED_SMEM>>>(leaves, out);
}